// round 1
// baseline (speedup 1.0000x reference)
#include <cuda_runtime.h>
#include <cuda_bf16.h>
#include <cstdint>

// AttentionBlock fused kernel, sm_103a.
// One CTA per (b,h) row: seq=64, c=256. All intermediates in SMEM.
// bf16 mma.sync tensor-core math, fp32 accumulation, fp32 residual.

#define SEQ   64
#define CH    256
#define LDH   264   // bf16 tile row stride in halves (528B: 16B-aligned, bank-conflict-free)
#define LDSS  68    // fp32 score tile stride (floats)
#define LDP   72    // bf16 P tile stride (144B, 16B-aligned)

// Pre-converted bf16 weights (scratch: __device__ globals, no allocation)
__device__ __nv_bfloat16 g_Wb[4][CH * CH];

__global__ void convw_kernel(const float* __restrict__ Wq, const float* __restrict__ Wk,
                             const float* __restrict__ Wv, const float* __restrict__ Wo) {
    int i = blockIdx.x * blockDim.x + threadIdx.x;
    if (i < CH * CH) {
        g_Wb[0][i] = __float2bfloat16(Wq[i]);
        g_Wb[1][i] = __float2bfloat16(Wk[i]);
        g_Wb[2][i] = __float2bfloat16(Wv[i]);
        g_Wb[3][i] = __float2bfloat16(Wo[i]);
    }
}

__device__ __forceinline__ uint32_t smem_u32(const void* p) {
    return (uint32_t)__cvta_generic_to_shared(p);
}

__device__ __forceinline__ void ldm_x4(uint32_t addr, uint32_t& a0, uint32_t& a1,
                                       uint32_t& a2, uint32_t& a3) {
    asm volatile("ldmatrix.sync.aligned.m8n8.x4.shared.b16 {%0,%1,%2,%3}, [%4];"
                 : "=r"(a0), "=r"(a1), "=r"(a2), "=r"(a3) : "r"(addr));
}
__device__ __forceinline__ void ldm_x2(uint32_t addr, uint32_t& b0, uint32_t& b1) {
    asm volatile("ldmatrix.sync.aligned.m8n8.x2.shared.b16 {%0,%1}, [%2];"
                 : "=r"(b0), "=r"(b1) : "r"(addr));
}
__device__ __forceinline__ void ldm_x2t(uint32_t addr, uint32_t& b0, uint32_t& b1) {
    asm volatile("ldmatrix.sync.aligned.m8n8.x2.trans.shared.b16 {%0,%1}, [%2];"
                 : "=r"(b0), "=r"(b1) : "r"(addr));
}
__device__ __forceinline__ void mma_bf16(float c[4],
                                         uint32_t a0, uint32_t a1, uint32_t a2, uint32_t a3,
                                         uint32_t b0, uint32_t b1) {
    asm volatile("mma.sync.aligned.m16n8k16.row.col.f32.bf16.bf16.f32 "
                 "{%0,%1,%2,%3}, {%4,%5,%6,%7}, {%8,%9}, {%0,%1,%2,%3};"
                 : "+f"(c[0]), "+f"(c[1]), "+f"(c[2]), "+f"(c[3])
                 : "r"(a0), "r"(a1), "r"(a2), "r"(a3), "r"(b0), "r"(b1));
}

// SMEM budget:
//   sX  64x264 bf16 = 33792   (x tile, later reused as O1 = P@V)
//   sQ  33792, sK 33792, sV 33792
//   sW  33792  (weight chunk [64][256]; fp32 score tile sS aliases this)
//   sP  64x72 bf16 = 9216
//   sBias 4*256 f32 = 4096
// total = 182272 bytes
#define SMEM_BYTES 182272

__global__ void __launch_bounds__(512, 1)
attn_kernel(const float* __restrict__ x,
            const float* __restrict__ bq, const float* __restrict__ bk,
            const float* __restrict__ bv, const float* __restrict__ bo,
            float* __restrict__ out)
{
    extern __shared__ char smem_raw[];
    __nv_bfloat16* sX = (__nv_bfloat16*)smem_raw;
    __nv_bfloat16* sQ = sX + SEQ * LDH;
    __nv_bfloat16* sK = sQ + SEQ * LDH;
    __nv_bfloat16* sV = sK + SEQ * LDH;
    __nv_bfloat16* sW = sV + SEQ * LDH;
    float*         sS = (float*)sW;                 // alias: scores live where W chunks do
    __nv_bfloat16* sP = sW + SEQ * LDH;
    float*      sBias = (float*)(sP + SEQ * LDP);

    const int tid  = threadIdx.x;
    const int wid  = tid >> 5;
    const int lane = tid & 31;
    const int grp  = lane >> 2;
    const int tig  = lane & 3;
    const int bh   = blockIdx.x;

    const float* xrow = x   + (size_t)bh * SEQ * CH;
    float*       orow = out + (size_t)bh * SEQ * CH;

    // ---------------- Phase 0: load biases + x tile (fp32 -> bf16) ----------------
    if (tid < CH) {
        sBias[tid]          = bq[tid];
        sBias[CH + tid]     = bk[tid];
        sBias[2 * CH + tid] = bv[tid];
        sBias[3 * CH + tid] = bo[tid];
    }
    {
        const float4* xv = (const float4*)xrow;
        #pragma unroll
        for (int t = 0; t < 8; t++) {
            int i = tid + t * 512;            // 4096 float4 total
            int row = i >> 6;
            int colf = (i & 63) * 4;
            float4 v = xv[i];
            __nv_bfloat162* d = (__nv_bfloat162*)(sX + row * LDH + colf);
            d[0] = __floats2bfloat162_rn(v.x, v.y);
            d[1] = __floats2bfloat162_rn(v.z, v.w);
        }
    }
    __syncthreads();

    const int rg = wid >> 2, cq = wid & 3;
    const int r0 = rg * 16;       // warp's 16 output rows
    const int nb = cq * 64;       // warp's 64 output cols (GEMM phases)

    // ---------------- Phase 2: Q/K/V = x @ W + b ----------------
    #pragma unroll 1
    for (int g = 0; g < 3; g++) {
        const uint4* Wg = (const uint4*)(g_Wb[g]);
        __nv_bfloat16* dst = (g == 0) ? sQ : (g == 1) ? sK : sV;
        float acc[8][4];
        #pragma unroll
        for (int nt = 0; nt < 8; nt++)
            acc[nt][0] = acc[nt][1] = acc[nt][2] = acc[nt][3] = 0.f;

        #pragma unroll 1
        for (int kc = 0; kc < 4; kc++) {
            // stream W chunk [64 k][256 n] bf16 into sW
            #pragma unroll
            for (int i = 0; i < 4; i++) {
                int j = tid + i * 512;        // 2048 uint4
                *(uint4*)(sW + (j >> 5) * LDH + (j & 31) * 8) = Wg[kc * 2048 + j];
            }
            __syncthreads();
            #pragma unroll
            for (int ks = 0; ks < 4; ks++) {
                uint32_t a0, a1, a2, a3;
                ldm_x4(smem_u32(sX + (r0 + (lane & 15)) * LDH
                                + kc * 64 + ks * 16 + ((lane >> 4) << 3)),
                       a0, a1, a2, a3);
                #pragma unroll
                for (int nt = 0; nt < 8; nt++) {
                    uint32_t b0, b1;
                    ldm_x2t(smem_u32(sW + (ks * 16 + (lane & 15)) * LDH + nb + nt * 8), b0, b1);
                    mma_bf16(acc[nt], a0, a1, a2, a3, b0, b1);
                }
            }
            __syncthreads();
        }
        // bias add + bf16 store
        #pragma unroll
        for (int nt = 0; nt < 8; nt++) {
            int col = nb + nt * 8 + tig * 2;
            float b0v = sBias[g * CH + col], b1v = sBias[g * CH + col + 1];
            *(__nv_bfloat162*)(dst + (r0 + grp) * LDH + col) =
                __floats2bfloat162_rn(acc[nt][0] + b0v, acc[nt][1] + b1v);
            *(__nv_bfloat162*)(dst + (r0 + grp + 8) * LDH + col) =
                __floats2bfloat162_rn(acc[nt][2] + b0v, acc[nt][3] + b1v);
        }
    }
    __syncthreads();

    // ---------------- Phase 3: S = (Q K^T) * scale ----------------
    {
        const int j0 = (wid & 3) * 16;    // 16 score cols per warp
        float sa[2][4] = {};
        #pragma unroll
        for (int ks = 0; ks < 16; ks++) {
            uint32_t a0, a1, a2, a3;
            ldm_x4(smem_u32(sQ + (r0 + (lane & 15)) * LDH + ks * 16 + ((lane >> 4) << 3)),
                   a0, a1, a2, a3);
            #pragma unroll
            for (int nt = 0; nt < 2; nt++) {
                uint32_t b0, b1;
                // B(k=c, n=j) = K[j][c]: non-trans ldmatrix on row-major K
                ldm_x2(smem_u32(sK + (j0 + nt * 8 + (lane & 7)) * LDH
                                + ks * 16 + (((lane >> 3) & 1) << 3)), b0, b1);
                mma_bf16(sa[nt], a0, a1, a2, a3, b0, b1);
            }
        }
        const float SCALE = 1.0f / (256.0f * 16.0f * 0.70710678118654752f);
        #pragma unroll
        for (int nt = 0; nt < 2; nt++) {
            int col = j0 + nt * 8 + tig * 2;
            sS[(r0 + grp) * LDSS + col]       = sa[nt][0] * SCALE;
            sS[(r0 + grp) * LDSS + col + 1]   = sa[nt][1] * SCALE;
            sS[(r0 + grp + 8) * LDSS + col]     = sa[nt][2] * SCALE;
            sS[(r0 + grp + 8) * LDSS + col + 1] = sa[nt][3] * SCALE;
        }
    }
    __syncthreads();

    // ---------------- Phase 4: softmax rows -> P (bf16) ----------------
    {
        int row = tid >> 3, s8 = tid & 7;      // 8 threads per row, 8 cols each
        const float* sr = sS + row * LDSS + s8 * 8;
        float v[8], e[8];
        #pragma unroll
        for (int i = 0; i < 8; i++) v[i] = sr[i];
        float m = v[0];
        #pragma unroll
        for (int i = 1; i < 8; i++) m = fmaxf(m, v[i]);
        #pragma unroll
        for (int d = 1; d < 8; d <<= 1) m = fmaxf(m, __shfl_xor_sync(0xffffffffu, m, d));
        float s = 0.f;
        #pragma unroll
        for (int i = 0; i < 8; i++) { e[i] = __expf(v[i] - m); s += e[i]; }
        #pragma unroll
        for (int d = 1; d < 8; d <<= 1) s += __shfl_xor_sync(0xffffffffu, s, d);
        float inv = 1.0f / s;
        __nv_bfloat162* dp = (__nv_bfloat162*)(sP + row * LDP + s8 * 8);
        #pragma unroll
        for (int i = 0; i < 4; i++)
            dp[i] = __floats2bfloat162_rn(e[2 * i] * inv, e[2 * i + 1] * inv);
    }
    __syncthreads();

    // ---------------- Phase 5: O1 = P @ V  (stored into sX) ----------------
    {
        float acc[8][4] = {};
        #pragma unroll
        for (int ks = 0; ks < 4; ks++) {
            uint32_t a0, a1, a2, a3;
            ldm_x4(smem_u32(sP + (r0 + (lane & 15)) * LDP + ks * 16 + ((lane >> 4) << 3)),
                   a0, a1, a2, a3);
            #pragma unroll
            for (int nt = 0; nt < 8; nt++) {
                uint32_t b0, b1;
                ldm_x2t(smem_u32(sV + (ks * 16 + (lane & 15)) * LDH + nb + nt * 8), b0, b1);
                mma_bf16(acc[nt], a0, a1, a2, a3, b0, b1);
            }
        }
        #pragma unroll
        for (int nt = 0; nt < 8; nt++) {
            int col = nb + nt * 8 + tig * 2;
            *(__nv_bfloat162*)(sX + (r0 + grp) * LDH + col) =
                __floats2bfloat162_rn(acc[nt][0], acc[nt][1]);
            *(__nv_bfloat162*)(sX + (r0 + grp + 8) * LDH + col) =
                __floats2bfloat162_rn(acc[nt][2], acc[nt][3]);
        }
    }
    __syncthreads();

    // ---------------- Phase 6: out = O1 @ Wo + bo + x ----------------
    {
        const uint4* Wg = (const uint4*)(g_Wb[3]);
        float acc[8][4] = {};
        #pragma unroll 1
        for (int kc = 0; kc < 4; kc++) {
            #pragma unroll
            for (int i = 0; i < 4; i++) {
                int j = tid + i * 512;
                *(uint4*)(sW + (j >> 5) * LDH + (j & 31) * 8) = Wg[kc * 2048 + j];
            }
            __syncthreads();
            #pragma unroll
            for (int ks = 0; ks < 4; ks++) {
                uint32_t a0, a1, a2, a3;
                ldm_x4(smem_u32(sX + (r0 + (lane & 15)) * LDH
                                + kc * 64 + ks * 16 + ((lane >> 4) << 3)),
                       a0, a1, a2, a3);
                #pragma unroll
                for (int nt = 0; nt < 8; nt++) {
                    uint32_t b0, b1;
                    ldm_x2t(smem_u32(sW + (ks * 16 + (lane & 15)) * LDH + nb + nt * 8), b0, b1);
                    mma_bf16(acc[nt], a0, a1, a2, a3, b0, b1);
                }
            }
            __syncthreads();
        }
        #pragma unroll
        for (int nt = 0; nt < 8; nt++) {
            int col = nb + nt * 8 + tig * 2;
            float b0v = sBias[3 * CH + col], b1v = sBias[3 * CH + col + 1];
            int ra = r0 + grp, rb = ra + 8;
            float2 xa = *(const float2*)(xrow + ra * CH + col);
            float2 xb = *(const float2*)(xrow + rb * CH + col);
            *(float2*)(orow + ra * CH + col) =
                make_float2(acc[nt][0] + b0v + xa.x, acc[nt][1] + b1v + xa.y);
            *(float2*)(orow + rb * CH + col) =
                make_float2(acc[nt][2] + b0v + xb.x, acc[nt][3] + b1v + xb.y);
        }
    }
}

extern "C" void kernel_launch(void* const* d_in, const int* in_sizes, int n_in,
                              void* d_out, int out_size) {
    const float* x  = (const float*)d_in[0];
    const float* Wq = (const float*)d_in[1];
    const float* bq = (const float*)d_in[2];
    const float* Wk = (const float*)d_in[3];
    const float* bk = (const float*)d_in[4];
    const float* Wv = (const float*)d_in[5];
    const float* bv = (const float*)d_in[6];
    const float* Wo = (const float*)d_in[7];
    const float* bo = (const float*)d_in[8];
    float* out = (float*)d_out;

    convw_kernel<<<256, 256>>>(Wq, Wk, Wv, Wo);

    // Idempotent; harness's correctness run sets it before capture too.
    cudaFuncSetAttribute(attn_kernel, cudaFuncAttributeMaxDynamicSharedMemorySize, SMEM_BYTES);
    attn_kernel<<<2048, 512, SMEM_BYTES>>>(x, bq, bk, bv, bo, out);
}